// round 6
// baseline (speedup 1.0000x reference)
#include <cuda_runtime.h>
#include <math.h>

typedef unsigned long long u64;
typedef unsigned short u16;
typedef unsigned char u8;

#define NN 4096
#define MM 20
#define HH 16
#define NX 32
#define NY 18
#define NLAB 3
#define NCELL (NLAB*NX*NY)   /* 1728 */
#define CAP 64
#define CAPC 28
#define SCAP 20480           /* shared CSR capacity (entries) */
#define NB 16
#define NT 1024
#define PI_F 3.14159274101257324f
#define QPI_F 0.785398185253143311f
#define COND 0.2f
#define IOUT 0.3f

// ---------------- global scratch ----------------
__device__ u64    g_tick;             // monotone ticket barrier counter (never reset)
__device__ int    g_rank[NN];
__device__ int    g_vt;
__device__ float  g_b7[NN*7];
__device__ float4 g_bev[NN];
__device__ float  g_area[NN];
__device__ int    g_cellid[NN];
__device__ int    g_cellcnt[NCELL];
__device__ u16    g_cellbox[NCELL*CAPC];
__device__ u16    g_pred[NN*CAP];
__device__ u16    g_succ[NN*CAP];
__device__ int    g_npred[NN], g_nsucc[NN];
__device__ int    g_nwork;
__device__ int    g_work[2048];
__device__ int    g_wcnt[2048];
__device__ u16    g_wmem[2048*MM];

// ---------------- dynamic shared (union of sort-phase and fix-phase) --------
// sort: keys u64[4096] @0 (32K) | bcnt int[4096] @32768 | bstart int[4096] @49152 | temp int[1024] @65536
// fix : offs int[4097] @0 (16.4K) | pdata u16[SCAP] @16512 | sts u8[4096] @57472 | sby u16[4096] @61568 | temp int[1024] @69760
#define S_KEYS   0
#define S_CNT    32768
#define S_START  49152
#define S_TEMP   65536
#define F_OFFS   0
#define F_PD     16512
#define F_STS    57472
#define F_SBY    61568
#define F_TMP    69760
#define SMEM_DYN 73856

// ---------------- replay-safe ticket grid barrier ----------------
__device__ __forceinline__ void gridbar() {
    __syncthreads();
    if (threadIdx.x == 0) {
        __threadfence();
        u64 my  = atomicAdd(&g_tick, 1ULL) + 1ULL;
        u64 tgt = ((my + NB - 1) / NB) * NB;
        while (*((volatile u64*)&g_tick) < tgt) { __nanosleep(64); }
        __threadfence();
    }
    __syncthreads();
}

__global__ __launch_bounds__(NT, 1) void k_all(
    const float* __restrict__ pb, const float* __restrict__ ps,
    const int* __restrict__ pl,
    const float* __restrict__ w1, const float* __restrict__ b1,
    const float* __restrict__ w2, const float* __restrict__ b2,
    const float* __restrict__ w3, const float* __restrict__ b3,
    float* __restrict__ out)
{
    extern __shared__ char sm[];
    __shared__ float s_w1[MM*HH], s_w2[HH*HH], s_w3[HH], s_b1[HH], s_b2[HH], s_b3v;
    __shared__ int s_done, s_useg;

    const int t = threadIdx.x;
    const int bid = blockIdx.x;

    // merge weights -> static shared (every block; used only in P4)
    for (int k = t; k < MM*HH; k += NT) s_w1[k] = w1[k];
    for (int k = t; k < HH*HH; k += NT) s_w2[k] = w2[k];
    if (t < HH) { s_w3[t] = w3[t]; s_b1[t] = b1[t]; s_b2[t] = b2[t]; }
    if (t == 0) s_b3v = b3[0];

    // ================= P0: bucket counting sort (block 0 only) =================
    if (bid == 0) {
        u64* keys   = (u64*)(sm + S_KEYS);
        int* bcnt   = (int*)(sm + S_CNT);
        int* bstart = (int*)(sm + S_START);
        int* temp   = (int*)(sm + S_TEMP);
        const int base = t * 4;

        if (t == 0) g_nwork = 0;
        for (int c = t; c < NCELL; c += NT) g_cellcnt[c] = 0;
        for (int b = t; b < NN; b += NT) bcnt[b] = 0;
        __syncthreads();

        unsigned keyv[4]; int bk[4]; int invc = 0;
        #pragma unroll
        for (int k = 0; k < 4; k++) {
            int i = base + k;
            float f = ps[i];
            if (f > COND) {
                unsigned u = __float_as_uint(f) | 0x80000000u;
                keyv[k] = ~u;
                int b = 4096 - (int)(f * 4096.0f);
                b = min(max(b, 0), 4095);
                bk[k] = b;
                atomicAdd(&bcnt[b], 1);
            } else { bk[k] = -1; invc++; }
        }
        __syncthreads();

        int myc[4]; int s0 = 0;
        #pragma unroll
        for (int k = 0; k < 4; k++) { myc[k] = bcnt[base + k]; s0 += myc[k]; }
        temp[t] = s0;
        __syncthreads();
        for (int off = 1; off < NT; off <<= 1) {
            int v = (t >= off) ? temp[t - off] : 0;
            __syncthreads();
            temp[t] += v;
            __syncthreads();
        }
        int vt = temp[NT-1];
        if (t == 0) g_vt = vt;
        int run = (t == 0) ? 0 : temp[t - 1];
        #pragma unroll
        for (int k = 0; k < 4; k++) { bstart[base + k] = run; run += myc[k]; }
        __syncthreads();

        temp[t] = invc;
        __syncthreads();
        for (int off = 1; off < NT; off <<= 1) {
            int v = (t >= off) ? temp[t - off] : 0;
            __syncthreads();
            temp[t] += v;
            __syncthreads();
        }
        int invBase = vt + ((t == 0) ? 0 : temp[t - 1]);

        int li = 0;
        #pragma unroll
        for (int k = 0; k < 4; k++) {
            int i = base + k;
            if (bk[k] >= 0) {
                int pos = atomicAdd(&bstart[bk[k]], 1);
                keys[pos] = ((u64)keyv[k] << 32) | (unsigned)i;
            } else {
                keys[invBase + li] = 0xFFFFFFFF00000000ull | (unsigned)i;
                li++;
            }
        }
        __syncthreads();

        for (int b = t; b < NN; b += NT) {
            int c = bcnt[b];
            if (c > 1) {
                int s = bstart[b] - c;
                for (int a = 1; a < c; a++) {
                    u64 v = keys[s + a];
                    int q = a - 1;
                    while (q >= 0 && keys[s + q] > v) { keys[s + q + 1] = keys[s + q]; q--; }
                    keys[s + q + 1] = v;
                }
            }
        }
        __syncthreads();

        #pragma unroll
        for (int k = 0; k < 4; k++) {
            int i = base + k;
            g_rank[(int)(keys[i] & 0xFFFFFFFFu)] = i;
        }
    }
    gridbar();

    // ================= P1: gather (256 items per block) =================
    if (t < 256) {
        int idx = bid * 256 + t;
        int i = g_rank[idx];

        float b[9];
        #pragma unroll
        for (int c = 0; c < 9; c++) b[c] = pb[idx*9 + c];
        #pragma unroll
        for (int c = 0; c < 7; c++) { g_b7[i*7 + c] = b[c]; out[i*9 + c] = b[c]; }
        out[i*9 + 7] = b[7];
        out[i*9 + 8] = b[8];
        out[NN*9  + i] = ps[idx];
        int lab = pl[idx];
        out[NN*10 + i] = (float)lab;

        float h   = b[6];
        float ang = h - floorf(h / PI_F + 0.5f) * PI_F;
        bool  sw  = fabsf(ang) >= QPI_F;
        float dx  = sw ? b[4] : b[3];
        float dy  = sw ? b[3] : b[4];
        float4 bv;
        bv.x = b[0] - dx * 0.5f;
        bv.y = b[1] - dy * 0.5f;
        bv.z = b[0] + dx * 0.5f;
        bv.w = b[1] + dy * 0.5f;
        g_bev[i]  = bv;
        g_area[i] = dx * dy;

        int cx = (int)floorf((b[0] + 70.0f) * (1.0f / 4.5f)); cx = min(max(cx, 0), NX-1);
        int cy = (int)floorf((b[1] + 40.0f) * (1.0f / 4.5f)); cy = min(max(cy, 0), NY-1);
        int cell = (lab * NY + cy) * NX + cx;
        g_cellid[i] = cell;
        int pos = atomicAdd(&g_cellcnt[cell], 1);
        if (pos < CAPC) g_cellbox[cell*CAPC + pos] = (u16)i;
    }
    gridbar();

    // ================= P2: build pred/succ lists (256 items per block) =================
    if (t < 256) {
        int i = bid * 256 + t;
        float4 a = g_bev[i];
        float aa = g_area[i];
        int cell = g_cellid[i];
        int cx = cell % NX, cy = (cell / NX) % NY, lab = cell / (NX * NY);
        int np = 0, ns = 0;
        for (int dy = -1; dy <= 1; dy++) {
            int yy = cy + dy; if (yy < 0 || yy >= NY) continue;
            for (int dx = -1; dx <= 1; dx++) {
                int xx = cx + dx; if (xx < 0 || xx >= NX) continue;
                int c2 = (lab * NY + yy) * NX + xx;
                int cnt2 = min(g_cellcnt[c2], CAPC);
                for (int p = 0; p < cnt2; p++) {
                    int j = g_cellbox[c2*CAPC + p];
                    if (j == i) continue;
                    float4 bb = g_bev[j];
                    float ix = fminf(a.z, bb.z) - fmaxf(a.x, bb.x);
                    float iy = fminf(a.w, bb.w) - fmaxf(a.y, bb.y);
                    float inter = fmaxf(ix, 0.0f) * fmaxf(iy, 0.0f);
                    float uni   = aa + g_area[j] - inter;
                    if (inter > IOUT * fmaxf(uni, 1e-6f)) {
                        if (j < i) { if (np < CAP) g_pred[i*CAP + np++] = (u16)j; }
                        else       { if (ns < CAP) g_succ[i*CAP + ns++] = (u16)j; }
                    }
                }
            }
        }
        for (int a2 = 1; a2 < ns; a2++) {
            u16 v = g_succ[i*CAP + a2];
            int b = a2 - 1;
            while (b >= 0 && g_succ[i*CAP + b] > v) { g_succ[i*CAP + b + 1] = g_succ[i*CAP + b]; b--; }
            g_succ[i*CAP + b + 1] = v;
        }
        g_npred[i] = np;
        g_nsucc[i] = ns;
    }
    gridbar();

    // ================= P3: fixpoint + suppby + worklist (block 0 only) =================
    if (bid == 0) {
        int* offs = (int*)(sm + F_OFFS);
        u16* pd   = (u16*)(sm + F_PD);
        u8*  sts  = (u8*)(sm + F_STS);
        u16* sby  = (u16*)(sm + F_SBY);
        int* temp = (int*)(sm + F_TMP);
        volatile u8* st = sts;
        const int base = t * 4;
        const int vt = g_vt;

        // CSR offsets from npred
        int np4[4]; int s0 = 0;
        #pragma unroll
        for (int k = 0; k < 4; k++) { np4[k] = g_npred[base + k]; s0 += np4[k]; }
        temp[t] = s0;
        __syncthreads();
        for (int off = 1; off < NT; off <<= 1) {
            int v = (t >= off) ? temp[t - off] : 0;
            __syncthreads();
            temp[t] += v;
            __syncthreads();
        }
        int run = (t == 0) ? 0 : temp[t - 1];
        #pragma unroll
        for (int k = 0; k < 4; k++) { offs[base + k] = run; run += np4[k]; }
        if (t == NT-1) offs[NN] = run;
        if (t == 0) s_useg = 0;
        __syncthreads();
        if (t == 0 && offs[NN] > SCAP) s_useg = 1;
        __syncthreads();
        if (!s_useg) {
            #pragma unroll
            for (int k = 0; k < 4; k++) {
                int i = base + k, o = offs[i];
                for (int p = 0; p < np4[k]; p++) pd[o + p] = g_pred[i*CAP + p];
            }
        }
        for (int i = t; i < NN; i += NT) sts[i] = (i < vt) ? 0 : 3;
        __syncthreads();
        const int useg = s_useg;

        // chaotic relaxation
        for (int round = 0; round < NN; round++) {
            if (t == 0) s_done = 1;
            __syncthreads();
            for (int i = t; i < vt; i += NT) {
                if (st[i] == 0) {
                    int o = offs[i], np = offs[i+1] - o;
                    bool anyK = false, allS = true;
                    for (int p = 0; p < np; p++) {
                        int j = useg ? (int)g_pred[i*CAP + p] : (int)pd[o + p];
                        u8 s = st[j];
                        anyK |= (s == 1);
                        allS &= (s >= 2);
                    }
                    if (anyK)      st[i] = 2;
                    else if (allS) st[i] = 1;
                    else           s_done = 0;
                }
            }
            __syncthreads();
            if (s_done) break;
        }

        // suppby + keep flags
        for (int i = t; i < NN; i += NT) {
            u8 s = sts[i];
            out[NN*11 + i] = (s == 1) ? 1.0f : 0.0f;
            u16 sb;
            if (s == 1) sb = (u16)i;
            else if (s == 3) sb = 0xFFFF;
            else {
                int o = offs[i], np = offs[i+1] - o;
                int best = 0xFFFF;
                for (int p = 0; p < np; p++) {
                    int q = useg ? (int)g_pred[i*CAP + p] : (int)pd[o + p];
                    if (sts[q] == 1 && q < best) best = q;
                }
                sb = (u16)best;
            }
            sby[i] = sb;
        }
        __syncthreads();

        // worklist of kept clusters with >1 member
        for (int i = t; i < NN; i += NT) {
            if (sts[i] != 1) continue;
            int ns = g_nsucc[i];
            u16 mem[MM];
            mem[0] = (u16)i;
            int cnt = 1, total = 1;
            for (int a = 0; a < ns; a++) {
                int j = g_succ[i*CAP + a];
                if ((int)sby[j] == i) { total++; if (cnt < MM) mem[cnt++] = (u16)j; }
            }
            if (total > 1) {
                int w = atomicAdd(&g_nwork, 1);
                g_work[w] = i;
                g_wcnt[w] = cnt;
                #pragma unroll
                for (int m = 0; m < MM; m++) if (m < cnt) g_wmem[w*MM + m] = mem[m];
            }
        }
    }
    gridbar();

    // ================= P4: merge MLP, one thread per (cluster, channel) =================
    {
        int gt = bid * NT + t;
        int w  = gt >> 3;
        int c  = gt & 7;
        if (c < 7 && w < g_nwork) {
            int i   = g_work[w];
            int cnt = g_wcnt[w];

            float h1[HH];
            #pragma unroll
            for (int h = 0; h < HH; h++) h1[h] = s_b1[h];
            for (int m = 0; m < cnt; m++) {
                int j = g_wmem[w*MM + m];
                float xv = g_b7[j*7 + c];
                #pragma unroll
                for (int h = 0; h < HH; h++) h1[h] += xv * s_w1[m*HH + h];
            }
            #pragma unroll
            for (int h = 0; h < HH; h++) h1[h] = fmaxf(h1[h], 0.0f);
            float h2[HH];
            #pragma unroll
            for (int q = 0; q < HH; q++) h2[q] = s_b2[q];
            #pragma unroll
            for (int h = 0; h < HH; h++) {
                float v = h1[h];
                #pragma unroll
                for (int q = 0; q < HH; q++) h2[q] += v * s_w2[h*HH + q];
            }
            float acc = s_b3v;
            #pragma unroll
            for (int q = 0; q < HH; q++) acc += fmaxf(h2[q], 0.0f) * s_w3[q];

            if (c >= 3 && c <= 5) acc = fmaxf(acc, 1e-5f);
            out[i*9 + c] = acc;
        }
    }
}

extern "C" void kernel_launch(void* const* d_in, const int* in_sizes, int n_in,
                              void* d_out, int out_size) {
    const float* pb = (const float*)d_in[0];
    const float* ps = (const float*)d_in[1];
    const int*   pl = (const int*)  d_in[2];
    const float* w1 = (const float*)d_in[3];
    const float* b1 = (const float*)d_in[4];
    const float* w2 = (const float*)d_in[5];
    const float* b2 = (const float*)d_in[6];
    const float* w3 = (const float*)d_in[7];
    const float* b3 = (const float*)d_in[8];
    float* out = (float*)d_out;

    cudaFuncSetAttribute(k_all, cudaFuncAttributeMaxDynamicSharedMemorySize, SMEM_DYN);
    k_all<<<NB, NT, SMEM_DYN>>>(pb, ps, pl, w1, b1, w2, b2, w3, b3, out);
}